// round 4
// baseline (speedup 1.0000x reference)
#include <cuda_runtime.h>
#include <cuda_bf16.h>
#include <stdint.h>
#include <math.h>

#define LQ    1024
#define LK    4096
#define NB    8
#define DM    256
#define NH    4
#define HD    (NH*DM)              /* 1024 */
#define Y_SIZE (LQ*NB*DM)          /* 2097152 */

typedef __nv_bfloat16  bf16;
typedef __nv_bfloat162 bf162;

/* ---------------- scratch (device globals; no allocation allowed) -------- */
__device__ bf16  g_qin_h[NB*LQ*DM],  g_qin_l[NB*LQ*DM];
__device__ bf16  g_kin_h[NB*LK*DM],  g_kin_l[NB*LK*DM];
__device__ bf16  g_vin_h[NB*LK*DM],  g_vin_l[NB*LK*DM];
__device__ bf16  g_Wq_h[HD*DM], g_Wq_l[HD*DM];
__device__ bf16  g_Wk_h[HD*DM], g_Wk_l[HD*DM];
__device__ bf16  g_Wv_h[HD*DM], g_Wv_l[HD*DM];
__device__ bf16  g_Wfc_h[DM*HD], g_Wfc_l[DM*HD];
__device__ bf16  g_Qh_h[NB*LQ*HD], g_Qh_l[NB*LQ*HD];
__device__ bf16  g_Kh_h[NB*LK*HD], g_Kh_l[NB*LK*HD];
__device__ bf16  g_Vh_h[NB*LK*HD], g_Vh_l[NB*LK*HD];
__device__ float g_logits[(long long)NB*NH*LQ*LK];
__device__ bf16  g_P_h[(long long)NB*NH*LQ*LK], g_P_l[(long long)NB*NH*LQ*LK];
__device__ bf16  g_O_h[NB*LQ*HD], g_O_l[NB*LQ*HD];
__device__ float g_fc[NB*LQ*DM];

/* ---------------- helpers ------------------------------------------------ */
__device__ __forceinline__ void split2(float a, float b, bf162& h, bf162& l) {
    bf16 ha = __float2bfloat16(a);
    bf16 hb = __float2bfloat16(b);
    h = __halves2bfloat162(ha, hb);
    l = __halves2bfloat162(__float2bfloat16(a - __bfloat162float(ha)),
                           __float2bfloat16(b - __bfloat162float(hb)));
}

__device__ __forceinline__ void cpa16(uint32_t dst, const void* src) {
    asm volatile("cp.async.cg.shared.global [%0], [%1], 16;" :: "r"(dst), "l"(src));
}
#define CP_COMMIT() asm volatile("cp.async.commit_group;")

#define LDSM4(R, addr) \
    asm volatile("ldmatrix.sync.aligned.m8n8.x4.shared.b16 {%0,%1,%2,%3}, [%4];" \
        : "=r"((R)[0]),"=r"((R)[1]),"=r"((R)[2]),"=r"((R)[3]) : "r"(addr))
#define LDSM4T(R, addr) \
    asm volatile("ldmatrix.sync.aligned.m8n8.x4.trans.shared.b16 {%0,%1,%2,%3}, [%4];" \
        : "=r"((R)[0]),"=r"((R)[1]),"=r"((R)[2]),"=r"((R)[3]) : "r"(addr))
#define MMA16816(D, A, B0, B1) \
    asm volatile("mma.sync.aligned.m16n8k16.row.col.f32.bf16.bf16.f32 " \
        "{%0,%1,%2,%3}, {%4,%5,%6,%7}, {%8,%9}, {%0,%1,%2,%3};" \
        : "+f"((D)[0]),"+f"((D)[1]),"+f"((D)[2]),"+f"((D)[3]) \
        : "r"((A)[0]),"r"((A)[1]),"r"((A)[2]),"r"((A)[3]), "r"(B0),"r"(B1))

/* ---------------- prep: seq-first -> batch-first (+pos adds), split ------ */
__global__ void prep_q_kernel(const float* __restrict__ tgt,
                              const float* __restrict__ qpos) {
    int t = (blockIdx.x * blockDim.x + threadIdx.x) * 4;
    if (t >= NB*LQ*DM) return;
    int d = t % DM;
    int r = t / DM;
    int q = r % LQ;
    int b = r / LQ;
    int src = (q*NB + b)*DM + d;
    float4 a = *(const float4*)(tgt  + src);
    float4 p = *(const float4*)(qpos + src);
    bf162 h01, l01, h23, l23;
    split2(a.x+p.x, a.y+p.y, h01, l01);
    split2(a.z+p.z, a.w+p.w, h23, l23);
    *(bf162*)(g_qin_h + t)     = h01;
    *(bf162*)(g_qin_h + t + 2) = h23;
    *(bf162*)(g_qin_l + t)     = l01;
    *(bf162*)(g_qin_l + t + 2) = l23;
}

__global__ void prep_kv_kernel(const float* __restrict__ mem,
                               const float* __restrict__ pos) {
    int t = (blockIdx.x * blockDim.x + threadIdx.x) * 4;
    if (t >= NB*LK*DM) return;
    int d = t % DM;
    int r = t / DM;
    int k = r % LK;
    int b = r / LK;
    int src = (k*NB + b)*DM + d;
    float4 m = *(const float4*)(mem + src);
    float4 p = *(const float4*)(pos + src);
    bf162 h01, l01, h23, l23;
    split2(m.x+p.x, m.y+p.y, h01, l01);
    split2(m.z+p.z, m.w+p.w, h23, l23);
    *(bf162*)(g_kin_h + t)     = h01;
    *(bf162*)(g_kin_h + t + 2) = h23;
    *(bf162*)(g_kin_l + t)     = l01;
    *(bf162*)(g_kin_l + t + 2) = l23;
    split2(m.x, m.y, h01, l01);
    split2(m.z, m.w, h23, l23);
    *(bf162*)(g_vin_h + t)     = h01;
    *(bf162*)(g_vin_h + t + 2) = h23;
    *(bf162*)(g_vin_l + t)     = l01;
    *(bf162*)(g_vin_l + t + 2) = l23;
}

/* ---------------- weight split conversion -------------------------------- */
__global__ void convw_kernel(const float* __restrict__ W,
                             bf16* __restrict__ Wh, bf16* __restrict__ Wl, int n) {
    int t = (blockIdx.x * blockDim.x + threadIdx.x) * 4;
    if (t >= n) return;
    float4 v = *(const float4*)(W + t);
    bf162 h01, l01, h23, l23;
    split2(v.x, v.y, h01, l01);
    split2(v.z, v.w, h23, l23);
    *(bf162*)(Wh + t)     = h01;
    *(bf162*)(Wh + t + 2) = h23;
    *(bf162*)(Wl + t)     = l01;
    *(bf162*)(Wl + t + 2) = l23;
}

/* ================== tensor-core GEMM (split-bf16, 3-pass, cp.async) ======
 * C = alpha * sum_k A[m,k] * (TRANS_B ? B[n,k] : B[k,n]); A,B = hi/lo planes.
 * CTA 128x128, 8 warps (4x2), warp 32x64, k-step 16, S-stage cp.async pipe.
 * ========================================================================= */
#define APITCH 40          /* bf16 elems/row: 16 hi + 16 lo + 8 pad (80 B)   */
#define BPITCH 136         /* NN: bf16 elems/row (128 data + 8 pad, 272 B)  */
#define ASTG  (128*APITCH)
#define BSTG_T (128*APITCH)
#define BSTG_N (32*BPITCH)

template<bool TRANS_B, bool OUT_SPLIT, int S>
__global__ void __launch_bounds__(256, 2)
gemm_tc(const bf16* __restrict__ Ah, const bf16* __restrict__ Al,
        const bf16* __restrict__ Bh, const bf16* __restrict__ Bl,
        float* __restrict__ C, bf16* __restrict__ Ch, bf16* __restrict__ Cl,
        int lda, int ldb, int ldc, int K, float alpha,
        long long sA0, long long sA1,
        long long sB0, long long sB1,
        long long sC0, long long sC1) {
    int z = blockIdx.z;
    int z0 = z / NH, z1 = z % NH;
    long long ao = z0*sA0 + z1*sA1;
    long long bo = z0*sB0 + z1*sB1;
    long long co = z0*sC0 + z1*sC1;
    Ah += ao; Al += ao;
    Bh += bo; Bl += bo;
    if (OUT_SPLIT) { Ch += co; Cl += co; } else { C += co; }

    const int m0 = blockIdx.y * 128;
    const int n0 = blockIdx.x * 128;

    const int tid  = threadIdx.x;
    const int lane = tid & 31;
    const int warp = tid >> 5;
    const int wm   = warp >> 1;
    const int wn   = warp & 1;

    extern __shared__ __align__(16) char dsm[];
    bf16* As = (bf16*)dsm;                 /* S * ASTG  */
    bf16* Bs = As + S*ASTG;                /* S * BSTG  */
    constexpr int BSTG = TRANS_B ? BSTG_T : BSTG_N;

    float acc[2][8][4];
    #pragma unroll
    for (int i = 0; i < 2; i++)
        #pragma unroll
        for (int j = 0; j < 8; j++)
            #pragma unroll
            for (int c = 0; c < 4; c++) acc[i][j][c] = 0.f;

    const int nk = K / 16;

    auto issue_stage = [&](int st, int k0) {
        uint32_t sA = (uint32_t)__cvta_generic_to_shared(As + st*ASTG);
        uint32_t sB = (uint32_t)__cvta_generic_to_shared(Bs + st*BSTG);
        #pragma unroll
        for (int c = tid; c < 512; c += 256) {
            int row  = c >> 2;
            int half = c & 1;
            int lo   = (c >> 1) & 1;
            const bf16* src = (lo ? Al : Ah) + (long long)(m0+row)*lda + k0 + half*8;
            cpa16(sA + row*80 + lo*32 + half*16, src);
        }
        if (TRANS_B) {
            #pragma unroll
            for (int c = tid; c < 512; c += 256) {
                int row  = c >> 2;
                int half = c & 1;
                int lo   = (c >> 1) & 1;
                const bf16* src = (lo ? Bl : Bh) + (long long)(n0+row)*ldb + k0 + half*8;
                cpa16(sB + row*80 + lo*32 + half*16, src);
            }
        } else {
            #pragma unroll
            for (int c = tid; c < 512; c += 256) {
                int plane = c >> 8;
                int rem   = c & 255;
                int kr    = rem >> 4;
                int ch    = rem & 15;
                const bf16* src = (plane ? Bl : Bh) + (long long)(k0+kr)*ldb + n0 + ch*8;
                cpa16(sB + (plane*16 + kr)*272 + ch*16, src);
            }
        }
        CP_COMMIT();
    };

    auto compute = [&](int st) {
        const bf16* Ab = As + st*ASTG;
        const bf16* Bb = Bs + st*BSTG;
        uint32_t a_h[2][4], a_l[2][4];
        #pragma unroll
        for (int mi = 0; mi < 2; mi++) {
            int row = wm*32 + mi*16 + (lane & 7) + ((lane >> 3) & 1)*8;
            uint32_t ad = (uint32_t)__cvta_generic_to_shared(
                Ab + row*APITCH + ((lane >> 4) & 1)*8);
            LDSM4(a_h[mi], ad);
            LDSM4(a_l[mi], ad + 32);
        }
        #pragma unroll
        for (int g = 0; g < 4; g++) {
            uint32_t bh[4], bl[4];
            if (TRANS_B) {
                int n = wn*64 + g*16 + (lane & 7) + ((lane >> 4) & 1)*8;
                uint32_t bd = (uint32_t)__cvta_generic_to_shared(
                    Bb + n*APITCH + ((lane >> 3) & 1)*8);
                LDSM4(bh, bd);
                LDSM4(bl, bd + 32);
            } else {
                int kr = (lane & 7) + ((lane >> 3) & 1)*8;
                int nc = wn*64 + g*16 + ((lane >> 4) & 1)*8;
                uint32_t bd = (uint32_t)__cvta_generic_to_shared(
                    Bb + kr*BPITCH + nc);
                LDSM4T(bh, bd);
                LDSM4T(bl, bd + 16*BPITCH*2);
            }
            #pragma unroll
            for (int t = 0; t < 2; t++) {
                #pragma unroll
                for (int mi = 0; mi < 2; mi++) {
                    float* d = acc[mi][g*2 + t];
                    MMA16816(d, a_h[mi], bh[2*t], bh[2*t+1]);
                    MMA16816(d, a_l[mi], bh[2*t], bh[2*t+1]);
                    MMA16816(d, a_h[mi], bl[2*t], bl[2*t+1]);
                }
            }
        }
    };

    #pragma unroll
    for (int s = 0; s < S-1; s++) issue_stage(s, s*16);

    for (int ks = 0; ks < nk; ks++) {
        asm volatile("cp.async.wait_group %0;" :: "n"(S-2));
        __syncthreads();
        compute(ks % S);
        int nx = ks + S - 1;
        if (nx < nk) issue_stage(nx % S, nx*16);
        else CP_COMMIT();
    }

    /* ---- epilogue ---- */
    #pragma unroll
    for (int mi = 0; mi < 2; mi++) {
        #pragma unroll
        for (int nj = 0; nj < 8; nj++) {
            int row = m0 + wm*32 + mi*16 + (lane >> 2);
            int col = n0 + wn*64 + nj*8 + (lane & 3)*2;
            float v0 = alpha*acc[mi][nj][0], v1 = alpha*acc[mi][nj][1];
            float v2 = alpha*acc[mi][nj][2], v3 = alpha*acc[mi][nj][3];
            if (OUT_SPLIT) {
                bf162 h, l;
                split2(v0, v1, h, l);
                *(bf162*)(Ch + (long long)row*ldc + col) = h;
                *(bf162*)(Cl + (long long)row*ldc + col) = l;
                split2(v2, v3, h, l);
                *(bf162*)(Ch + (long long)(row+8)*ldc + col) = h;
                *(bf162*)(Cl + (long long)(row+8)*ldc + col) = l;
            } else {
                float2 a; a.x = v0; a.y = v1;
                float2 b; b.x = v2; b.y = v3;
                *(float2*)(C + (long long)row*ldc + col)     = a;
                *(float2*)(C + (long long)(row+8)*ldc + col) = b;
            }
        }
    }
}

/* ---------------- fused softmax + head-mean; attn -> split planes -------- */
__device__ __forceinline__ float blk_reduce_max(float v, float* red) {
    red[threadIdx.x] = v; __syncthreads();
    for (int s = 128; s > 0; s >>= 1) {
        if (threadIdx.x < s) red[threadIdx.x] = fmaxf(red[threadIdx.x], red[threadIdx.x+s]);
        __syncthreads();
    }
    float r = red[0]; __syncthreads(); return r;
}
__device__ __forceinline__ float blk_reduce_sum(float v, float* red) {
    red[threadIdx.x] = v; __syncthreads();
    for (int s = 128; s > 0; s >>= 1) {
        if (threadIdx.x < s) red[threadIdx.x] += red[threadIdx.x+s];
        __syncthreads();
    }
    float r = red[0]; __syncthreads(); return r;
}

__global__ void __launch_bounds__(256)
softmax_mean_kernel(float* __restrict__ out_mean) {
    const int row = blockIdx.x;      /* b*LQ + q */
    const int b = row / LQ;
    const int q = row % LQ;
    const int tid = threadIdx.x;
    __shared__ float red[256];

    float mean_acc[LK/256];
    #pragma unroll
    for (int i = 0; i < LK/256; i++) mean_acc[i] = 0.f;

    for (int h = 0; h < NH; h++) {
        long long off = ((long long)((b*NH + h)*LQ + q)) * LK;
        const float* base = g_logits + off;
        float v[LK/256];
        float mx = -1e30f;
        #pragma unroll
        for (int i = 0; i < LK/256; i++) {
            v[i] = base[i*256 + tid];
            mean_acc[i] += v[i];
            mx = fmaxf(mx, v[i]);
        }
        mx = blk_reduce_max(mx, red);
        float s = 0.f;
        #pragma unroll
        for (int i = 0; i < LK/256; i++) { v[i] = expf(v[i] - mx); s += v[i]; }
        s = blk_reduce_sum(s, red);
        float inv = 1.f / s;
        bf16* ph = g_P_h + off;
        bf16* pl = g_P_l + off;
        #pragma unroll
        for (int i = 0; i < LK/256; i++) {
            float p = v[i] * inv;
            bf16 hp = __float2bfloat16(p);
            ph[i*256 + tid] = hp;
            pl[i*256 + tid] = __float2bfloat16(p - __bfloat162float(hp));
        }
    }
    float* mdst = out_mean + (long long)row * LK;
    #pragma unroll
    for (int i = 0; i < LK/256; i++) mdst[i*256 + tid] = mean_acc[i] * 0.25f;
}

/* ---------------- residual + LayerNorm ----------------------------------- */
__global__ void __launch_bounds__(256)
ln_kernel(const float* __restrict__ tgt,
          const float* __restrict__ gamma,
          const float* __restrict__ beta,
          float* __restrict__ y) {
    const int row = blockIdx.x;
    const int b = row / LQ;
    const int q = row % LQ;
    const int d = threadIdx.x;
    __shared__ float red[256];

    float x = g_fc[row*DM + d] + tgt[(q*NB + b)*DM + d];
    float mu = blk_reduce_sum(x, red) * (1.f/DM);
    float diff = x - mu;
    float var = blk_reduce_sum(diff*diff, red) * (1.f/DM);
    y[(q*NB + b)*DM + d] = diff * rsqrtf(var + 1e-5f) * gamma[d] + beta[d];
}

/* ---------------- launch ------------------------------------------------- */
#define STAGES 4
#define SMEM_T (STAGES*(ASTG + BSTG_T)*2)   /* 81920 */
#define SMEM_N (STAGES*(ASTG + BSTG_N)*2)   /* 75776 */

extern "C" void kernel_launch(void* const* d_in, const int* in_sizes, int n_in,
                              void* d_out, int out_size) {
    const float* tgt  = (const float*)d_in[0];
    const float* mem  = (const float*)d_in[1];
    const float* pos  = (const float*)d_in[2];
    const float* qpos = (const float*)d_in[3];
    const float* Wq   = (const float*)d_in[4];
    const float* Wk   = (const float*)d_in[5];
    const float* Wv   = (const float*)d_in[6];
    const float* Wfc  = (const float*)d_in[7];
    const float* ln_g = (const float*)d_in[8];
    const float* ln_b = (const float*)d_in[9];
    float* out = (float*)d_out;

    static int attr_done = 0;
    if (!attr_done) {
        cudaFuncSetAttribute((const void*)gemm_tc<true,  true,  STAGES>,
                             cudaFuncAttributeMaxDynamicSharedMemorySize, SMEM_T);
        cudaFuncSetAttribute((const void*)gemm_tc<true,  false, STAGES>,
                             cudaFuncAttributeMaxDynamicSharedMemorySize, SMEM_T);
        cudaFuncSetAttribute((const void*)gemm_tc<false, true,  STAGES>,
                             cudaFuncAttributeMaxDynamicSharedMemorySize, SMEM_N);
        attr_done = 1;
    }

    bf16 *qin_h,*qin_l,*kin_h,*kin_l,*vin_h,*vin_l;
    bf16 *Wq_h,*Wq_l,*Wk_h,*Wk_l,*Wv_h,*Wv_l,*Wfc_h,*Wfc_l;
    bf16 *Qh_h,*Qh_l,*Kh_h,*Kh_l,*Vh_h,*Vh_l,*P_h,*P_l,*O_h,*O_l;
    float *logits,*fc;
    cudaGetSymbolAddress((void**)&qin_h, g_qin_h); cudaGetSymbolAddress((void**)&qin_l, g_qin_l);
    cudaGetSymbolAddress((void**)&kin_h, g_kin_h); cudaGetSymbolAddress((void**)&kin_l, g_kin_l);
    cudaGetSymbolAddress((void**)&vin_h, g_vin_h); cudaGetSymbolAddress((void**)&vin_l, g_vin_l);
    cudaGetSymbolAddress((void**)&Wq_h,  g_Wq_h);  cudaGetSymbolAddress((void**)&Wq_l,  g_Wq_l);
    cudaGetSymbolAddress((void**)&Wk_h,  g_Wk_h);  cudaGetSymbolAddress((void**)&Wk_l,  g_Wk_l);
    cudaGetSymbolAddress((void**)&Wv_h,  g_Wv_h);  cudaGetSymbolAddress((void**)&Wv_l,  g_Wv_l);
    cudaGetSymbolAddress((void**)&Wfc_h, g_Wfc_h); cudaGetSymbolAddress((void**)&Wfc_l, g_Wfc_l);
    cudaGetSymbolAddress((void**)&Qh_h,  g_Qh_h);  cudaGetSymbolAddress((void**)&Qh_l,  g_Qh_l);
    cudaGetSymbolAddress((void**)&Kh_h,  g_Kh_h);  cudaGetSymbolAddress((void**)&Kh_l,  g_Kh_l);
    cudaGetSymbolAddress((void**)&Vh_h,  g_Vh_h);  cudaGetSymbolAddress((void**)&Vh_l,  g_Vh_l);
    cudaGetSymbolAddress((void**)&P_h,   g_P_h);   cudaGetSymbolAddress((void**)&P_l,   g_P_l);
    cudaGetSymbolAddress((void**)&O_h,   g_O_h);   cudaGetSymbolAddress((void**)&O_l,   g_O_l);
    cudaGetSymbolAddress((void**)&logits, g_logits);
    cudaGetSymbolAddress((void**)&fc,     g_fc);

    /* 1) transpose + pos adds + split, and weight split */
    prep_q_kernel <<<(NB*LQ*DM/4 + 255)/256, 256>>>(tgt, qpos);
    prep_kv_kernel<<<(NB*LK*DM/4 + 255)/256, 256>>>(mem, pos);
    convw_kernel<<<(HD*DM/4 + 255)/256, 256>>>(Wq,  Wq_h,  Wq_l,  HD*DM);
    convw_kernel<<<(HD*DM/4 + 255)/256, 256>>>(Wk,  Wk_h,  Wk_l,  HD*DM);
    convw_kernel<<<(HD*DM/4 + 255)/256, 256>>>(Wv,  Wv_h,  Wv_l,  HD*DM);
    convw_kernel<<<(DM*HD/4 + 255)/256, 256>>>(Wfc, Wfc_h, Wfc_l, DM*HD);

    /* 2) projections (NT, split out) */
    {
        dim3 g(HD/128, (NB*LQ)/128, 1);
        gemm_tc<true,true,STAGES><<<g, 256, SMEM_T>>>(qin_h,qin_l, Wq_h,Wq_l,
            nullptr, Qh_h, Qh_l, DM, DM, HD, DM, 1.f, 0,0, 0,0, 0,0);
    }
    {
        dim3 g(HD/128, (NB*LK)/128, 1);
        gemm_tc<true,true,STAGES><<<g, 256, SMEM_T>>>(kin_h,kin_l, Wk_h,Wk_l,
            nullptr, Kh_h, Kh_l, DM, DM, HD, DM, 1.f, 0,0, 0,0, 0,0);
        gemm_tc<true,true,STAGES><<<g, 256, SMEM_T>>>(vin_h,vin_l, Wv_h,Wv_l,
            nullptr, Vh_h, Vh_l, DM, DM, HD, DM, 1.f, 0,0, 0,0, 0,0);
    }

    /* 3) logits = (1/16) * Qh @ Kh^T  (fp32 out) */
    {
        dim3 g(LK/128, LQ/128, NB*NH);
        gemm_tc<true,false,STAGES><<<g, 256, SMEM_T>>>(Qh_h,Qh_l, Kh_h,Kh_l,
            logits, nullptr, nullptr, HD, HD, LK, DM, 0.0625f,
            (long long)LQ*HD, DM,
            (long long)LK*HD, DM,
            (long long)NH*LQ*LK, (long long)LQ*LK);
    }

    /* 4) softmax -> split attn planes + head-mean into d_out tail */
    softmax_mean_kernel<<<NB*LQ, 256>>>(out + Y_SIZE);

    /* 5) O = attn @ Vh (NN, split out) */
    {
        dim3 g(DM/128, LQ/128, NB*NH);
        gemm_tc<false,true,STAGES><<<g, 256, SMEM_N>>>(P_h,P_l, Vh_h,Vh_l,
            nullptr, O_h, O_l, LK, HD, HD, LK, 1.f,
            (long long)NH*LQ*LK, (long long)LQ*LK,
            (long long)LK*HD, DM,
            (long long)LQ*HD, DM);
    }

    /* 6) fc (NT, fp32 out) */
    {
        dim3 g(DM/128, (NB*LQ)/128, 1);
        gemm_tc<true,false,STAGES><<<g, 256, SMEM_T>>>(O_h,O_l, Wfc_h,Wfc_l,
            fc, nullptr, nullptr, HD, HD, DM, HD, 1.f, 0,0, 0,0, 0,0);
    }

    /* 7) residual + LayerNorm -> y */
    ln_kernel<<<NB*LQ, 256>>>(tgt, ln_g, ln_b, out);
}

// round 5
// speedup vs baseline: 1.6565x; 1.6565x over previous
#include <cuda_runtime.h>
#include <cuda_bf16.h>
#include <stdint.h>
#include <math.h>

#define LQ    1024
#define LK    4096
#define NB    8
#define DM    256
#define NH    4
#define HD    (NH*DM)              /* 1024 */
#define Y_SIZE (LQ*NB*DM)          /* 2097152 */

typedef __nv_bfloat16  bf16;
typedef __nv_bfloat162 bf162;

/* ---------------- scratch (device globals; no allocation allowed) -------- */
__device__ bf16  g_qin_h[NB*LQ*DM],  g_qin_l[NB*LQ*DM];
__device__ bf16  g_kin_h[NB*LK*DM],  g_kin_l[NB*LK*DM];
__device__ bf16  g_vin_h[NB*LK*DM],  g_vin_l[NB*LK*DM];
__device__ bf16  g_Wq_h[HD*DM],  g_Wq_l[HD*DM];
__device__ bf16  g_Wk_h[HD*DM],  g_Wk_l[HD*DM];
__device__ bf16  g_Wv_h[HD*DM],  g_Wv_l[HD*DM];
__device__ bf16  g_Wfc_h[DM*HD], g_Wfc_l[DM*HD];
__device__ bf16  g_Qh_h[NB*LQ*HD], g_Qh_l[NB*LQ*HD];
__device__ bf16  g_Kh_h[NB*LK*HD], g_Kh_l[NB*LK*HD];
__device__ bf16  g_Vh_h[NB*LK*HD], g_Vh_l[NB*LK*HD];
__device__ float g_logits[(long long)NB*NH*LQ*LK];
__device__ bf16  g_P[(long long)NB*NH*LQ*LK];
__device__ bf16  g_O_h[NB*LQ*HD], g_O_l[NB*LQ*HD];
__device__ float g_fc[NB*LQ*DM];

/* ---------------- helpers ------------------------------------------------ */
__device__ __forceinline__ void split2(float a, float b, bf162& h, bf162& l) {
    bf16 ha = __float2bfloat16(a);
    bf16 hb = __float2bfloat16(b);
    h = __halves2bfloat162(ha, hb);
    l = __halves2bfloat162(__float2bfloat16(a - __bfloat162float(ha)),
                           __float2bfloat16(b - __bfloat162float(hb)));
}

#define LDSM4(R, addr) \
    asm volatile("ldmatrix.sync.aligned.m8n8.x4.shared.b16 {%0,%1,%2,%3}, [%4];" \
        : "=r"((R)[0]),"=r"((R)[1]),"=r"((R)[2]),"=r"((R)[3]) : "r"(addr))
#define LDSM4T(R, addr) \
    asm volatile("ldmatrix.sync.aligned.m8n8.x4.trans.shared.b16 {%0,%1,%2,%3}, [%4];" \
        : "=r"((R)[0]),"=r"((R)[1]),"=r"((R)[2]),"=r"((R)[3]) : "r"(addr))
#define MMA16816(D, A, B0, B1) \
    asm volatile("mma.sync.aligned.m16n8k16.row.col.f32.bf16.bf16.f32 " \
        "{%0,%1,%2,%3}, {%4,%5,%6,%7}, {%8,%9}, {%0,%1,%2,%3};" \
        : "+f"((D)[0]),"+f"((D)[1]),"+f"((D)[2]),"+f"((D)[3]) \
        : "r"((A)[0]),"r"((A)[1]),"r"((A)[2]),"r"((A)[3]), "r"(B0),"r"(B1))

/* ---------------- prep: seq-first -> batch-first (+pos adds), split ------ */
__global__ void prep_q_kernel(const float* __restrict__ tgt,
                              const float* __restrict__ qpos) {
    int t = (blockIdx.x * blockDim.x + threadIdx.x) * 4;
    if (t >= NB*LQ*DM) return;
    int d = t % DM;
    int r = t / DM;
    int q = r % LQ;
    int b = r / LQ;
    int src = (q*NB + b)*DM + d;
    float4 a = *(const float4*)(tgt  + src);
    float4 p = *(const float4*)(qpos + src);
    bf162 h01, l01, h23, l23;
    split2(a.x+p.x, a.y+p.y, h01, l01);
    split2(a.z+p.z, a.w+p.w, h23, l23);
    *(bf162*)(g_qin_h + t)     = h01;
    *(bf162*)(g_qin_h + t + 2) = h23;
    *(bf162*)(g_qin_l + t)     = l01;
    *(bf162*)(g_qin_l + t + 2) = l23;
}

__global__ void prep_kv_kernel(const float* __restrict__ mem,
                               const float* __restrict__ pos) {
    int t = (blockIdx.x * blockDim.x + threadIdx.x) * 4;
    if (t >= NB*LK*DM) return;
    int d = t % DM;
    int r = t / DM;
    int k = r % LK;
    int b = r / LK;
    int src = (k*NB + b)*DM + d;
    float4 m = *(const float4*)(mem + src);
    float4 p = *(const float4*)(pos + src);
    bf162 h01, l01, h23, l23;
    split2(m.x+p.x, m.y+p.y, h01, l01);
    split2(m.z+p.z, m.w+p.w, h23, l23);
    *(bf162*)(g_kin_h + t)     = h01;
    *(bf162*)(g_kin_h + t + 2) = h23;
    *(bf162*)(g_kin_l + t)     = l01;
    *(bf162*)(g_kin_l + t + 2) = l23;
    split2(m.x, m.y, h01, l01);
    split2(m.z, m.w, h23, l23);
    *(bf162*)(g_vin_h + t)     = h01;
    *(bf162*)(g_vin_h + t + 2) = h23;
    *(bf162*)(g_vin_l + t)     = l01;
    *(bf162*)(g_vin_l + t + 2) = l23;
}

__global__ void convw_kernel(const float* __restrict__ W,
                             bf16* __restrict__ Wh, bf16* __restrict__ Wl, int n) {
    int t = (blockIdx.x * blockDim.x + threadIdx.x) * 4;
    if (t >= n) return;
    float4 v = *(const float4*)(W + t);
    bf162 h01, l01, h23, l23;
    split2(v.x, v.y, h01, l01);
    split2(v.z, v.w, h23, l23);
    *(bf162*)(Wh + t)     = h01;
    *(bf162*)(Wh + t + 2) = h23;
    *(bf162*)(Wl + t)     = l01;
    *(bf162*)(Wl + t + 2) = l23;
}

/* ================== tensor-core GEMM (pre-split bf16 planes) =============
 * C = alpha * sum_k A[m,k] * (TRANS_B ? B[n,k] : B[k,n])
 * A: hi(+lo if A_SPLIT) bf16 planes.  B: hi+lo planes.
 * Passes: AhBh (+AlBh if A_SPLIT) + AhBl.
 * CTA 128x128, 8 warps (4x2), warp 32x64, k-step 16,
 * double-buffered smem + register prefetch (R3-proven schedule).
 * ========================================================================= */
#define APITCH 40          /* bf16/row: 16 hi + 16 lo + 8 pad (80 B) */
#define BPITCH 136         /* NN: bf16/row (128 data + 8 pad, 272 B) */

template<bool TRANS_B, bool A_SPLIT, bool OUT_SPLIT>
__global__ void __launch_bounds__(256)
gemm_tc(const bf16* __restrict__ Ah, const bf16* __restrict__ Al,
        const bf16* __restrict__ Bh, const bf16* __restrict__ Bl,
        float* __restrict__ C, bf16* __restrict__ Ch, bf16* __restrict__ Cl,
        int lda, int ldb, int ldc, int K, float alpha,
        long long sA0, long long sA1,
        long long sB0, long long sB1,
        long long sC0, long long sC1) {
    int z = blockIdx.z;
    int z0 = z / NH, z1 = z % NH;
    long long ao = z0*sA0 + z1*sA1;
    long long bo = z0*sB0 + z1*sB1;
    long long co = z0*sC0 + z1*sC1;
    Ah += ao; if (A_SPLIT) Al += ao;
    Bh += bo; Bl += bo;
    if (OUT_SPLIT) { Ch += co; Cl += co; } else { C += co; }

    const int m0 = blockIdx.y * 128;
    const int n0 = blockIdx.x * 128;

    const int tid  = threadIdx.x;
    const int lane = tid & 31;
    const int warp = tid >> 5;
    const int wm   = warp >> 1;
    const int wn   = warp & 1;

    constexpr int BSZ = TRANS_B ? 128*APITCH : 32*BPITCH;
    __shared__ __align__(16) bf16 As[2][128*APITCH];
    __shared__ __align__(16) bf16 Bs[2][BSZ];

    /* loader mapping */
    const int la_row = tid >> 1;          /* 0..127 */
    const int la_h8  = (tid & 1) * 8;     /* 0 or 8 (bf16 elems) */
    const int lb_kr  = tid >> 4;          /* NN: 0..15 */
    const int lb_c8  = (tid & 15) * 8;    /* NN: 0..120 */

    uint4 pa_h, pa_l, pb_h, pb_l;

    float acc[2][8][4];
    #pragma unroll
    for (int i = 0; i < 2; i++)
        #pragma unroll
        for (int j = 0; j < 8; j++)
            #pragma unroll
            for (int c = 0; c < 4; c++) acc[i][j][c] = 0.f;

    const int nk = K / 16;

    auto g_load = [&](int k0) {
        pa_h = *(const uint4*)(Ah + (long long)(m0 + la_row)*lda + k0 + la_h8);
        if (A_SPLIT)
            pa_l = *(const uint4*)(Al + (long long)(m0 + la_row)*lda + k0 + la_h8);
        if (TRANS_B) {
            pb_h = *(const uint4*)(Bh + (long long)(n0 + la_row)*ldb + k0 + la_h8);
            pb_l = *(const uint4*)(Bl + (long long)(n0 + la_row)*ldb + k0 + la_h8);
        } else {
            pb_h = *(const uint4*)(Bh + (long long)(k0 + lb_kr)*ldb + n0 + lb_c8);
            pb_l = *(const uint4*)(Bl + (long long)(k0 + lb_kr)*ldb + n0 + lb_c8);
        }
    };

    auto s_store = [&](int buf) {
        *(uint4*)&As[buf][la_row*APITCH + la_h8] = pa_h;
        if (A_SPLIT)
            *(uint4*)&As[buf][la_row*APITCH + 16 + la_h8] = pa_l;
        if (TRANS_B) {
            *(uint4*)&Bs[buf][la_row*APITCH + la_h8] = pb_h;
            *(uint4*)&Bs[buf][la_row*APITCH + 16 + la_h8] = pb_l;
        } else {
            *(uint4*)&Bs[buf][lb_kr*BPITCH + lb_c8]        = pb_h;
            *(uint4*)&Bs[buf][(16 + lb_kr)*BPITCH + lb_c8] = pb_l;
        }
    };

    auto compute = [&](int buf) {
        uint32_t a_h[2][4], a_l[2][4];
        #pragma unroll
        for (int mi = 0; mi < 2; mi++) {
            int row = wm*32 + mi*16 + (lane & 7) + ((lane >> 3) & 1)*8;
            uint32_t ad = (uint32_t)__cvta_generic_to_shared(
                &As[buf][row*APITCH + ((lane >> 4) & 1)*8]);
            LDSM4(a_h[mi], ad);
            if (A_SPLIT) LDSM4(a_l[mi], ad + 32);
        }
        #pragma unroll
        for (int g = 0; g < 4; g++) {
            uint32_t bh[4], bl[4];
            if (TRANS_B) {
                int n = wn*64 + g*16 + (lane & 7) + ((lane >> 4) & 1)*8;
                uint32_t bd = (uint32_t)__cvta_generic_to_shared(
                    &Bs[buf][n*APITCH + ((lane >> 3) & 1)*8]);
                LDSM4(bh, bd);
                LDSM4(bl, bd + 32);
            } else {
                int kr = (lane & 7) + ((lane >> 3) & 1)*8;
                int nc = wn*64 + g*16 + ((lane >> 4) & 1)*8;
                uint32_t bd = (uint32_t)__cvta_generic_to_shared(
                    &Bs[buf][kr*BPITCH + nc]);
                LDSM4T(bh, bd);
                LDSM4T(bl, bd + 16*BPITCH*2);
            }
            #pragma unroll
            for (int t = 0; t < 2; t++) {
                #pragma unroll
                for (int mi = 0; mi < 2; mi++) {
                    float* d = acc[mi][g*2 + t];
                    MMA16816(d, a_h[mi], bh[2*t], bh[2*t+1]);
                    if (A_SPLIT) MMA16816(d, a_l[mi], bh[2*t], bh[2*t+1]);
                    MMA16816(d, a_h[mi], bl[2*t], bl[2*t+1]);
                }
            }
        }
    };

    g_load(0);
    s_store(0);
    __syncthreads();

    for (int ks = 0; ks < nk; ks++) {
        int buf = ks & 1;
        bool more = (ks + 1) < nk;
        if (more) g_load((ks + 1) * 16);
        compute(buf);
        if (more) s_store(buf ^ 1);
        __syncthreads();
    }

    /* ---- epilogue ---- */
    #pragma unroll
    for (int mi = 0; mi < 2; mi++) {
        #pragma unroll
        for (int nj = 0; nj < 8; nj++) {
            int row = m0 + wm*32 + mi*16 + (lane >> 2);
            int col = n0 + wn*64 + nj*8 + (lane & 3)*2;
            float v0 = alpha*acc[mi][nj][0], v1 = alpha*acc[mi][nj][1];
            float v2 = alpha*acc[mi][nj][2], v3 = alpha*acc[mi][nj][3];
            if (OUT_SPLIT) {
                bf162 h, l;
                split2(v0, v1, h, l);
                *(bf162*)(Ch + (long long)row*ldc + col) = h;
                *(bf162*)(Cl + (long long)row*ldc + col) = l;
                split2(v2, v3, h, l);
                *(bf162*)(Ch + (long long)(row+8)*ldc + col) = h;
                *(bf162*)(Cl + (long long)(row+8)*ldc + col) = l;
            } else {
                float2 a; a.x = v0; a.y = v1;
                float2 b; b.x = v2; b.y = v3;
                *(float2*)(C + (long long)row*ldc + col)     = a;
                *(float2*)(C + (long long)(row+8)*ldc + col) = b;
            }
        }
    }
}

/* ---------------- fused softmax (P -> bf16) + head-mean ------------------ */
__device__ __forceinline__ float blk_reduce_max(float v, float* red) {
    red[threadIdx.x] = v; __syncthreads();
    for (int s = 128; s > 0; s >>= 1) {
        if (threadIdx.x < s) red[threadIdx.x] = fmaxf(red[threadIdx.x], red[threadIdx.x+s]);
        __syncthreads();
    }
    float r = red[0]; __syncthreads(); return r;
}
__device__ __forceinline__ float blk_reduce_sum(float v, float* red) {
    red[threadIdx.x] = v; __syncthreads();
    for (int s = 128; s > 0; s >>= 1) {
        if (threadIdx.x < s) red[threadIdx.x] += red[threadIdx.x+s];
        __syncthreads();
    }
    float r = red[0]; __syncthreads(); return r;
}

__global__ void __launch_bounds__(256)
softmax_mean_kernel(float* __restrict__ out_mean) {
    const int row = blockIdx.x;      /* b*LQ + q */
    const int b = row / LQ;
    const int q = row % LQ;
    const int tid = threadIdx.x;
    __shared__ float red[256];

    float mean_acc[LK/256];
    #pragma unroll
    for (int i = 0; i < LK/256; i++) mean_acc[i] = 0.f;

    for (int h = 0; h < NH; h++) {
        long long off = ((long long)((b*NH + h)*LQ + q)) * LK;
        const float* base = g_logits + off;
        float v[LK/256];
        float mx = -1e30f;
        #pragma unroll
        for (int i = 0; i < LK/256; i++) {
            v[i] = base[i*256 + tid];
            mean_acc[i] += v[i];
            mx = fmaxf(mx, v[i]);
        }
        mx = blk_reduce_max(mx, red);
        float s = 0.f;
        #pragma unroll
        for (int i = 0; i < LK/256; i++) { v[i] = expf(v[i] - mx); s += v[i]; }
        s = blk_reduce_sum(s, red);
        float inv = 1.f / s;
        bf16* pdst = g_P + off;
        #pragma unroll
        for (int i = 0; i < LK/256; i++)
            pdst[i*256 + tid] = __float2bfloat16(v[i] * inv);
    }
    float* mdst = out_mean + (long long)row * LK;
    #pragma unroll
    for (int i = 0; i < LK/256; i++) mdst[i*256 + tid] = mean_acc[i] * 0.25f;
}

/* ---------------- residual + LayerNorm ----------------------------------- */
__global__ void __launch_bounds__(256)
ln_kernel(const float* __restrict__ tgt,
          const float* __restrict__ gamma,
          const float* __restrict__ beta,
          float* __restrict__ y) {
    const int row = blockIdx.x;
    const int b = row / LQ;
    const int q = row % LQ;
    const int d = threadIdx.x;
    __shared__ float red[256];

    float x = g_fc[row*DM + d] + tgt[(q*NB + b)*DM + d];
    float mu = blk_reduce_sum(x, red) * (1.f/DM);
    float diff = x - mu;
    float var = blk_reduce_sum(diff*diff, red) * (1.f/DM);
    y[(q*NB + b)*DM + d] = diff * rsqrtf(var + 1e-5f) * gamma[d] + beta[d];
}

/* ---------------- launch ------------------------------------------------- */
extern "C" void kernel_launch(void* const* d_in, const int* in_sizes, int n_in,
                              void* d_out, int out_size) {
    const float* tgt  = (const float*)d_in[0];
    const float* mem  = (const float*)d_in[1];
    const float* pos  = (const float*)d_in[2];
    const float* qpos = (const float*)d_in[3];
    const float* Wq   = (const float*)d_in[4];
    const float* Wk   = (const float*)d_in[5];
    const float* Wv   = (const float*)d_in[6];
    const float* Wfc  = (const float*)d_in[7];
    const float* ln_g = (const float*)d_in[8];
    const float* ln_b = (const float*)d_in[9];
    float* out = (float*)d_out;

    bf16 *qin_h,*qin_l,*kin_h,*kin_l,*vin_h,*vin_l;
    bf16 *Wq_h,*Wq_l,*Wk_h,*Wk_l,*Wv_h,*Wv_l,*Wfc_h,*Wfc_l;
    bf16 *Qh_h,*Qh_l,*Kh_h,*Kh_l,*Vh_h,*Vh_l,*P,*O_h,*O_l;
    float *logits,*fc;
    cudaGetSymbolAddress((void**)&qin_h, g_qin_h); cudaGetSymbolAddress((void**)&qin_l, g_qin_l);
    cudaGetSymbolAddress((void**)&kin_h, g_kin_h); cudaGetSymbolAddress((void**)&kin_l, g_kin_l);
    cudaGetSymbolAddress((void**)&vin_h, g_vin_h); cudaGetSymbolAddress((void**)&vin_l, g_vin_l);
    cudaGetSymbolAddress((void**)&Wq_h,  g_Wq_h);  cudaGetSymbolAddress((void**)&Wq_l,  g_Wq_l);
    cudaGetSymbolAddress((void**)&Wk_h,  g_Wk_h);  cudaGetSymbolAddress((void**)&Wk_l,  g_Wk_l);
    cudaGetSymbolAddress((void**)&Wv_h,  g_Wv_h);  cudaGetSymbolAddress((void**)&Wv_l,  g_Wv_l);
    cudaGetSymbolAddress((void**)&Wfc_h, g_Wfc_h); cudaGetSymbolAddress((void**)&Wfc_l, g_Wfc_l);
    cudaGetSymbolAddress((void**)&Qh_h,  g_Qh_h);  cudaGetSymbolAddress((void**)&Qh_l,  g_Qh_l);
    cudaGetSymbolAddress((void**)&Kh_h,  g_Kh_h);  cudaGetSymbolAddress((void**)&Kh_l,  g_Kh_l);
    cudaGetSymbolAddress((void**)&Vh_h,  g_Vh_h);  cudaGetSymbolAddress((void**)&Vh_l,  g_Vh_l);
    cudaGetSymbolAddress((void**)&P,     g_P);
    cudaGetSymbolAddress((void**)&O_h,   g_O_h);   cudaGetSymbolAddress((void**)&O_l,   g_O_l);
    cudaGetSymbolAddress((void**)&logits, g_logits);
    cudaGetSymbolAddress((void**)&fc,     g_fc);

    /* 1) transpose + pos adds + split; weight split */
    prep_q_kernel <<<(NB*LQ*DM/4 + 255)/256, 256>>>(tgt, qpos);
    prep_kv_kernel<<<(NB*LK*DM/4 + 255)/256, 256>>>(mem, pos);
    convw_kernel<<<(HD*DM/4 + 255)/256, 256>>>(Wq,  Wq_h,  Wq_l,  HD*DM);
    convw_kernel<<<(HD*DM/4 + 255)/256, 256>>>(Wk,  Wk_h,  Wk_l,  HD*DM);
    convw_kernel<<<(HD*DM/4 + 255)/256, 256>>>(Wv,  Wv_h,  Wv_l,  HD*DM);
    convw_kernel<<<(DM*HD/4 + 255)/256, 256>>>(Wfc, Wfc_h, Wfc_l, DM*HD);

    /* 2) projections (NT, split out) */
    {
        dim3 g(HD/128, (NB*LQ)/128, 1);
        gemm_tc<true,true,true><<<g, 256>>>(qin_h,qin_l, Wq_h,Wq_l,
            nullptr, Qh_h, Qh_l, DM, DM, HD, DM, 1.f, 0,0, 0,0, 0,0);
    }
    {
        dim3 g(HD/128, (NB*LK)/128, 1);
        gemm_tc<true,true,true><<<g, 256>>>(kin_h,kin_l, Wk_h,Wk_l,
            nullptr, Kh_h, Kh_l, DM, DM, HD, DM, 1.f, 0,0, 0,0, 0,0);
        gemm_tc<true,true,true><<<g, 256>>>(vin_h,vin_l, Wv_h,Wv_l,
            nullptr, Vh_h, Vh_l, DM, DM, HD, DM, 1.f, 0,0, 0,0, 0,0);
    }

    /* 3) logits = (1/16) * Qh @ Kh^T  (fp32 out) */
    {
        dim3 g(LK/128, LQ/128, NB*NH);
        gemm_tc<true,true,false><<<g, 256>>>(Qh_h,Qh_l, Kh_h,Kh_l,
            logits, nullptr, nullptr, HD, HD, LK, DM, 0.0625f,
            (long long)LQ*HD, DM,
            (long long)LK*HD, DM,
            (long long)NH*LQ*LK, (long long)LQ*LK);
    }

    /* 4) softmax -> bf16 P + head-mean into d_out tail */
    softmax_mean_kernel<<<NB*LQ, 256>>>(out + Y_SIZE);

    /* 5) O = P @ Vh (NN, A single-plane, split out) */
    {
        dim3 g(DM/128, LQ/128, NB*NH);
        gemm_tc<false,false,true><<<g, 256>>>(P, nullptr, Vh_h,Vh_l,
            nullptr, O_h, O_l, LK, HD, HD, LK, 1.f,
            (long long)NH*LQ*LK, (long long)LQ*LK,
            (long long)LK*HD, DM,
            (long long)LQ*HD, DM);
    }

    /* 6) fc (NT, fp32 out) */
    {
        dim3 g(DM/128, (NB*LQ)/128, 1);
        gemm_tc<true,true,false><<<g, 256>>>(O_h,O_l, Wfc_h,Wfc_l,
            fc, nullptr, nullptr, HD, HD, DM, HD, 1.f, 0,0, 0,0, 0,0);
    }

    /* 7) residual + LayerNorm -> y */
    ln_kernel<<<NB*LQ, 256>>>(tgt, ln_g, ln_b, out);
}

// round 6
// speedup vs baseline: 1.6768x; 1.0123x over previous
#include <cuda_runtime.h>
#include <cuda_bf16.h>
#include <stdint.h>
#include <math.h>

#define LQ    1024
#define LK    4096
#define NB    8
#define DM    256
#define NH    4
#define HD    (NH*DM)              /* 1024 */
#define Y_SIZE (LQ*NB*DM)          /* 2097152 */

typedef __nv_bfloat16  bf16;
typedef __nv_bfloat162 bf162;

/* ---------------- scratch (device globals; no allocation allowed) -------- */
__device__ bf16  g_qin_h[NB*LQ*DM],  g_qin_l[NB*LQ*DM];
__device__ bf16  g_kin_h[NB*LK*DM],  g_kin_l[NB*LK*DM];
__device__ bf16  g_vin_h[NB*LK*DM],  g_vin_l[NB*LK*DM];
__device__ bf16  g_Wq_h[HD*DM],  g_Wq_l[HD*DM];
__device__ bf16  g_Wk_h[HD*DM],  g_Wk_l[HD*DM];
__device__ bf16  g_Wv_h[HD*DM],  g_Wv_l[HD*DM];
__device__ bf16  g_Wfc_h[DM*HD], g_Wfc_l[DM*HD];
__device__ bf16  g_Qh_h[NB*LQ*HD], g_Qh_l[NB*LQ*HD];
__device__ bf16  g_Kh_h[NB*LK*HD], g_Kh_l[NB*LK*HD];
__device__ bf16  g_Vh_h[NB*LK*HD], g_Vh_l[NB*LK*HD];
__device__ float g_logits[(long long)NB*NH*LQ*LK];
__device__ bf16  g_P[(long long)NB*NH*LQ*LK];
__device__ bf16  g_O_h[NB*LQ*HD], g_O_l[NB*LQ*HD];
__device__ float g_fc[NB*LQ*DM];

/* ---------------- helpers ------------------------------------------------ */
__device__ __forceinline__ void split2(float a, float b, bf162& h, bf162& l) {
    bf16 ha = __float2bfloat16(a);
    bf16 hb = __float2bfloat16(b);
    h = __halves2bfloat162(ha, hb);
    l = __halves2bfloat162(__float2bfloat16(a - __bfloat162float(ha)),
                           __float2bfloat16(b - __bfloat162float(hb)));
}

#define LDSM4(R, addr) \
    asm volatile("ldmatrix.sync.aligned.m8n8.x4.shared.b16 {%0,%1,%2,%3}, [%4];" \
        : "=r"((R)[0]),"=r"((R)[1]),"=r"((R)[2]),"=r"((R)[3]) : "r"(addr))
#define LDSM4T(R, addr) \
    asm volatile("ldmatrix.sync.aligned.m8n8.x4.trans.shared.b16 {%0,%1,%2,%3}, [%4];" \
        : "=r"((R)[0]),"=r"((R)[1]),"=r"((R)[2]),"=r"((R)[3]) : "r"(addr))
#define MMA16816(D, A, B0, B1) \
    asm volatile("mma.sync.aligned.m16n8k16.row.col.f32.bf16.bf16.f32 " \
        "{%0,%1,%2,%3}, {%4,%5,%6,%7}, {%8,%9}, {%0,%1,%2,%3};" \
        : "+f"((D)[0]),"+f"((D)[1]),"+f"((D)[2]),"+f"((D)[3]) \
        : "r"((A)[0]),"r"((A)[1]),"r"((A)[2]),"r"((A)[3]), "r"(B0),"r"(B1))

/* ---------------- prep: seq-first -> batch-first (+pos adds), split ------ */
__global__ void prep_q_kernel(const float* __restrict__ tgt,
                              const float* __restrict__ qpos) {
    int t = (blockIdx.x * blockDim.x + threadIdx.x) * 4;
    if (t >= NB*LQ*DM) return;
    int d = t % DM;
    int r = t / DM;
    int q = r % LQ;
    int b = r / LQ;
    int src = (q*NB + b)*DM + d;
    float4 a = *(const float4*)(tgt  + src);
    float4 p = *(const float4*)(qpos + src);
    bf162 h01, l01, h23, l23;
    split2(a.x+p.x, a.y+p.y, h01, l01);
    split2(a.z+p.z, a.w+p.w, h23, l23);
    *(bf162*)(g_qin_h + t)     = h01;
    *(bf162*)(g_qin_h + t + 2) = h23;
    *(bf162*)(g_qin_l + t)     = l01;
    *(bf162*)(g_qin_l + t + 2) = l23;
}

__global__ void prep_kv_kernel(const float* __restrict__ mem,
                               const float* __restrict__ pos) {
    int t = (blockIdx.x * blockDim.x + threadIdx.x) * 4;
    if (t >= NB*LK*DM) return;
    int d = t % DM;
    int r = t / DM;
    int k = r % LK;
    int b = r / LK;
    int src = (k*NB + b)*DM + d;
    float4 m = *(const float4*)(mem + src);
    float4 p = *(const float4*)(pos + src);
    bf162 h01, l01, h23, l23;
    split2(m.x+p.x, m.y+p.y, h01, l01);
    split2(m.z+p.z, m.w+p.w, h23, l23);
    *(bf162*)(g_kin_h + t)     = h01;
    *(bf162*)(g_kin_h + t + 2) = h23;
    *(bf162*)(g_kin_l + t)     = l01;
    *(bf162*)(g_kin_l + t + 2) = l23;
    split2(m.x, m.y, h01, l01);
    split2(m.z, m.w, h23, l23);
    *(bf162*)(g_vin_h + t)     = h01;
    *(bf162*)(g_vin_h + t + 2) = h23;
    *(bf162*)(g_vin_l + t)     = l01;
    *(bf162*)(g_vin_l + t + 2) = l23;
}

__global__ void convw_kernel(const float* __restrict__ W,
                             bf16* __restrict__ Wh, bf16* __restrict__ Wl, int n) {
    int t = (blockIdx.x * blockDim.x + threadIdx.x) * 4;
    if (t >= n) return;
    float4 v = *(const float4*)(W + t);
    bf162 h01, l01, h23, l23;
    split2(v.x, v.y, h01, l01);
    split2(v.z, v.w, h23, l23);
    *(bf162*)(Wh + t)     = h01;
    *(bf162*)(Wh + t + 2) = h23;
    *(bf162*)(Wl + t)     = l01;
    *(bf162*)(Wl + t + 2) = l23;
}

/* ================== tensor-core GEMM (pre-split bf16 planes) =============
 * C = alpha * sum_k A[m,k] * (TRANS_B ? B[n,k] : B[k,n])
 * A: hi(+lo if A_SPLIT) bf16 planes.  B: hi+lo planes.
 * Passes: AhBh (+AlBh if A_SPLIT) + AhBl — issued pass-major so the 4
 * accumulator tiles between same-tile reuses hide HMMA accumulator latency.
 * CTA 128x128, 8 warps (4x2), warp 32x64, k-step 16, double-buffered smem.
 * ========================================================================= */
#define APITCH 40          /* bf16/row: 16 hi + 16 lo + 8 pad (80 B) */
#define BPITCH 136         /* NN: bf16/row (128 data + 8 pad, 272 B) */

template<bool TRANS_B, bool A_SPLIT, bool OUT_SPLIT>
__global__ void __launch_bounds__(256)
gemm_tc(const bf16* __restrict__ Ah, const bf16* __restrict__ Al,
        const bf16* __restrict__ Bh, const bf16* __restrict__ Bl,
        float* __restrict__ C, bf16* __restrict__ Ch, bf16* __restrict__ Cl,
        int lda, int ldb, int ldc, int K, float alpha,
        long long sA0, long long sA1,
        long long sB0, long long sB1,
        long long sC0, long long sC1) {
    int z = blockIdx.z;
    int z0 = z / NH, z1 = z % NH;
    long long ao = z0*sA0 + z1*sA1;
    long long bo = z0*sB0 + z1*sB1;
    long long co = z0*sC0 + z1*sC1;
    Ah += ao; if (A_SPLIT) Al += ao;
    Bh += bo; Bl += bo;
    if (OUT_SPLIT) { Ch += co; Cl += co; } else { C += co; }

    const int m0 = blockIdx.y * 128;
    const int n0 = blockIdx.x * 128;

    const int tid  = threadIdx.x;
    const int lane = tid & 31;
    const int warp = tid >> 5;
    const int wm   = warp >> 1;
    const int wn   = warp & 1;

    constexpr int BSZ = TRANS_B ? 128*APITCH : 32*BPITCH;
    __shared__ __align__(16) bf16 As[2][128*APITCH];
    __shared__ __align__(16) bf16 Bs[2][BSZ];

    /* loader mapping */
    const int la_row = tid >> 1;          /* 0..127 */
    const int la_h8  = (tid & 1) * 8;     /* 0 or 8 (bf16 elems) */
    const int lb_kr  = tid >> 4;          /* NN: 0..15 */
    const int lb_c8  = (tid & 15) * 8;    /* NN: 0..120 */

    uint4 pa_h, pa_l, pb_h, pb_l;

    float acc[2][8][4];
    #pragma unroll
    for (int i = 0; i < 2; i++)
        #pragma unroll
        for (int j = 0; j < 8; j++)
            #pragma unroll
            for (int c = 0; c < 4; c++) acc[i][j][c] = 0.f;

    const int nk = K / 16;

    auto g_load = [&](int k0) {
        pa_h = *(const uint4*)(Ah + (long long)(m0 + la_row)*lda + k0 + la_h8);
        if (A_SPLIT)
            pa_l = *(const uint4*)(Al + (long long)(m0 + la_row)*lda + k0 + la_h8);
        if (TRANS_B) {
            pb_h = *(const uint4*)(Bh + (long long)(n0 + la_row)*ldb + k0 + la_h8);
            pb_l = *(const uint4*)(Bl + (long long)(n0 + la_row)*ldb + k0 + la_h8);
        } else {
            pb_h = *(const uint4*)(Bh + (long long)(k0 + lb_kr)*ldb + n0 + lb_c8);
            pb_l = *(const uint4*)(Bl + (long long)(k0 + lb_kr)*ldb + n0 + lb_c8);
        }
    };

    auto s_store = [&](int buf) {
        *(uint4*)&As[buf][la_row*APITCH + la_h8] = pa_h;
        if (A_SPLIT)
            *(uint4*)&As[buf][la_row*APITCH + 16 + la_h8] = pa_l;
        if (TRANS_B) {
            *(uint4*)&Bs[buf][la_row*APITCH + la_h8] = pb_h;
            *(uint4*)&Bs[buf][la_row*APITCH + 16 + la_h8] = pb_l;
        } else {
            *(uint4*)&Bs[buf][lb_kr*BPITCH + lb_c8]        = pb_h;
            *(uint4*)&Bs[buf][(16 + lb_kr)*BPITCH + lb_c8] = pb_l;
        }
    };

    auto compute = [&](int buf) {
        uint32_t a_h[2][4], a_l[2][4];
        #pragma unroll
        for (int mi = 0; mi < 2; mi++) {
            int row = wm*32 + mi*16 + (lane & 7) + ((lane >> 3) & 1)*8;
            uint32_t ad = (uint32_t)__cvta_generic_to_shared(
                &As[buf][row*APITCH + ((lane >> 4) & 1)*8]);
            LDSM4(a_h[mi], ad);
            if (A_SPLIT) LDSM4(a_l[mi], ad + 32);
        }
        #pragma unroll
        for (int g = 0; g < 4; g++) {
            uint32_t bh[4], bl[4];
            if (TRANS_B) {
                int n = wn*64 + g*16 + (lane & 7) + ((lane >> 4) & 1)*8;
                uint32_t bd = (uint32_t)__cvta_generic_to_shared(
                    &Bs[buf][n*APITCH + ((lane >> 3) & 1)*8]);
                LDSM4(bh, bd);
                LDSM4(bl, bd + 32);
            } else {
                int kr = (lane & 7) + ((lane >> 3) & 1)*8;
                int nc = wn*64 + g*16 + ((lane >> 4) & 1)*8;
                uint32_t bd = (uint32_t)__cvta_generic_to_shared(
                    &Bs[buf][kr*BPITCH + nc]);
                LDSM4T(bh, bd);
                LDSM4T(bl, bd + 16*BPITCH*2);
            }
            /* pass-major issue order: 4 independent accumulators per pass,
             * same-acc reuse distance = 4 MMAs (hides HMMA acc latency) */
            #pragma unroll
            for (int t = 0; t < 2; t++)
                #pragma unroll
                for (int mi = 0; mi < 2; mi++)
                    MMA16816(acc[mi][g*2 + t], a_h[mi], bh[2*t], bh[2*t+1]);
            if (A_SPLIT) {
                #pragma unroll
                for (int t = 0; t < 2; t++)
                    #pragma unroll
                    for (int mi = 0; mi < 2; mi++)
                        MMA16816(acc[mi][g*2 + t], a_l[mi], bh[2*t], bh[2*t+1]);
            }
            #pragma unroll
            for (int t = 0; t < 2; t++)
                #pragma unroll
                for (int mi = 0; mi < 2; mi++)
                    MMA16816(acc[mi][g*2 + t], a_h[mi], bl[2*t], bl[2*t+1]);
        }
    };

    g_load(0);
    s_store(0);
    __syncthreads();

    for (int ks = 0; ks < nk; ks++) {
        int buf = ks & 1;
        bool more = (ks + 1) < nk;
        if (more) g_load((ks + 1) * 16);
        compute(buf);
        if (more) s_store(buf ^ 1);
        __syncthreads();
    }

    /* ---- epilogue ---- */
    #pragma unroll
    for (int mi = 0; mi < 2; mi++) {
        #pragma unroll
        for (int nj = 0; nj < 8; nj++) {
            int row = m0 + wm*32 + mi*16 + (lane >> 2);
            int col = n0 + wn*64 + nj*8 + (lane & 3)*2;
            float v0 = alpha*acc[mi][nj][0], v1 = alpha*acc[mi][nj][1];
            float v2 = alpha*acc[mi][nj][2], v3 = alpha*acc[mi][nj][3];
            if (OUT_SPLIT) {
                bf162 h, l;
                split2(v0, v1, h, l);
                *(bf162*)(Ch + (long long)row*ldc + col) = h;
                *(bf162*)(Cl + (long long)row*ldc + col) = l;
                split2(v2, v3, h, l);
                *(bf162*)(Ch + (long long)(row+8)*ldc + col) = h;
                *(bf162*)(Cl + (long long)(row+8)*ldc + col) = l;
            } else {
                float2 a; a.x = v0; a.y = v1;
                float2 b; b.x = v2; b.y = v3;
                *(float2*)(C + (long long)row*ldc + col)     = a;
                *(float2*)(C + (long long)(row+8)*ldc + col) = b;
            }
        }
    }
}

/* ---------------- fused softmax (P -> bf16) + head-mean ------------------ */
__device__ __forceinline__ float blk_reduce_max(float v, float* red) {
    red[threadIdx.x] = v; __syncthreads();
    for (int s = 128; s > 0; s >>= 1) {
        if (threadIdx.x < s) red[threadIdx.x] = fmaxf(red[threadIdx.x], red[threadIdx.x+s]);
        __syncthreads();
    }
    float r = red[0]; __syncthreads(); return r;
}
__device__ __forceinline__ float blk_reduce_sum(float v, float* red) {
    red[threadIdx.x] = v; __syncthreads();
    for (int s = 128; s > 0; s >>= 1) {
        if (threadIdx.x < s) red[threadIdx.x] += red[threadIdx.x+s];
        __syncthreads();
    }
    float r = red[0]; __syncthreads(); return r;
}

__global__ void __launch_bounds__(256)
softmax_mean_kernel(float* __restrict__ out_mean) {
    const int row = blockIdx.x;      /* b*LQ + q */
    const int b = row / LQ;
    const int q = row % LQ;
    const int tid = threadIdx.x;
    __shared__ float red[256];

    float mean_acc[LK/256];
    #pragma unroll
    for (int i = 0; i < LK/256; i++) mean_acc[i] = 0.f;

    for (int h = 0; h < NH; h++) {
        long long off = ((long long)((b*NH + h)*LQ + q)) * LK;
        const float* base = g_logits + off;
        float v[LK/256];
        float mx = -1e30f;
        #pragma unroll
        for (int i = 0; i < LK/256; i++) {
            v[i] = base[i*256 + tid];
            mean_acc[i] += v[i];
            mx = fmaxf(mx, v[i]);
        }
        mx = blk_reduce_max(mx, red);
        float s = 0.f;
        #pragma unroll
        for (int i = 0; i < LK/256; i++) { v[i] = __expf(v[i] - mx); s += v[i]; }
        s = blk_reduce_sum(s, red);
        float inv = 1.f / s;
        bf16* pdst = g_P + off;
        #pragma unroll
        for (int i = 0; i < LK/256; i++)
            pdst[i*256 + tid] = __float2bfloat16(v[i] * inv);
    }
    float* mdst = out_mean + (long long)row * LK;
    #pragma unroll
    for (int i = 0; i < LK/256; i++) mdst[i*256 + tid] = mean_acc[i] * 0.25f;
}

/* ---------------- residual + LayerNorm ----------------------------------- */
__global__ void __launch_bounds__(256)
ln_kernel(const float* __restrict__ tgt,
          const float* __restrict__ gamma,
          const float* __restrict__ beta,
          float* __restrict__ y) {
    const int row = blockIdx.x;
    const int b = row / LQ;
    const int q = row % LQ;
    const int d = threadIdx.x;
    __shared__ float red[256];

    float x = g_fc[row*DM + d] + tgt[(q*NB + b)*DM + d];
    float mu = blk_reduce_sum(x, red) * (1.f/DM);
    float diff = x - mu;
    float var = blk_reduce_sum(diff*diff, red) * (1.f/DM);
    y[(q*NB + b)*DM + d] = diff * rsqrtf(var + 1e-5f) * gamma[d] + beta[d];
}

/* ---------------- launch ------------------------------------------------- */
extern "C" void kernel_launch(void* const* d_in, const int* in_sizes, int n_in,
                              void* d_out, int out_size) {
    const float* tgt  = (const float*)d_in[0];
    const float* mem  = (const float*)d_in[1];
    const float* pos  = (const float*)d_in[2];
    const float* qpos = (const float*)d_in[3];
    const float* Wq   = (const float*)d_in[4];
    const float* Wk   = (const float*)d_in[5];
    const float* Wv   = (const float*)d_in[6];
    const float* Wfc  = (const float*)d_in[7];
    const float* ln_g = (const float*)d_in[8];
    const float* ln_b = (const float*)d_in[9];
    float* out = (float*)d_out;

    bf16 *qin_h,*qin_l,*kin_h,*kin_l,*vin_h,*vin_l;
    bf16 *Wq_h,*Wq_l,*Wk_h,*Wk_l,*Wv_h,*Wv_l,*Wfc_h,*Wfc_l;
    bf16 *Qh_h,*Qh_l,*Kh_h,*Kh_l,*Vh_h,*Vh_l,*P,*O_h,*O_l;
    float *logits,*fc;
    cudaGetSymbolAddress((void**)&qin_h, g_qin_h); cudaGetSymbolAddress((void**)&qin_l, g_qin_l);
    cudaGetSymbolAddress((void**)&kin_h, g_kin_h); cudaGetSymbolAddress((void**)&kin_l, g_kin_l);
    cudaGetSymbolAddress((void**)&vin_h, g_vin_h); cudaGetSymbolAddress((void**)&vin_l, g_vin_l);
    cudaGetSymbolAddress((void**)&Wq_h,  g_Wq_h);  cudaGetSymbolAddress((void**)&Wq_l,  g_Wq_l);
    cudaGetSymbolAddress((void**)&Wk_h,  g_Wk_h);  cudaGetSymbolAddress((void**)&Wk_l,  g_Wk_l);
    cudaGetSymbolAddress((void**)&Wv_h,  g_Wv_h);  cudaGetSymbolAddress((void**)&Wv_l,  g_Wv_l);
    cudaGetSymbolAddress((void**)&Wfc_h, g_Wfc_h); cudaGetSymbolAddress((void**)&Wfc_l, g_Wfc_l);
    cudaGetSymbolAddress((void**)&Qh_h,  g_Qh_h);  cudaGetSymbolAddress((void**)&Qh_l,  g_Qh_l);
    cudaGetSymbolAddress((void**)&Kh_h,  g_Kh_h);  cudaGetSymbolAddress((void**)&Kh_l,  g_Kh_l);
    cudaGetSymbolAddress((void**)&Vh_h,  g_Vh_h);  cudaGetSymbolAddress((void**)&Vh_l,  g_Vh_l);
    cudaGetSymbolAddress((void**)&P,     g_P);
    cudaGetSymbolAddress((void**)&O_h,   g_O_h);   cudaGetSymbolAddress((void**)&O_l,   g_O_l);
    cudaGetSymbolAddress((void**)&logits, g_logits);
    cudaGetSymbolAddress((void**)&fc,     g_fc);

    /* 1) transpose + pos adds + split; weight split */
    prep_q_kernel <<<(NB*LQ*DM/4 + 255)/256, 256>>>(tgt, qpos);
    prep_kv_kernel<<<(NB*LK*DM/4 + 255)/256, 256>>>(mem, pos);
    convw_kernel<<<(HD*DM/4 + 255)/256, 256>>>(Wq,  Wq_h,  Wq_l,  HD*DM);
    convw_kernel<<<(HD*DM/4 + 255)/256, 256>>>(Wk,  Wk_h,  Wk_l,  HD*DM);
    convw_kernel<<<(HD*DM/4 + 255)/256, 256>>>(Wv,  Wv_h,  Wv_l,  HD*DM);
    convw_kernel<<<(DM*HD/4 + 255)/256, 256>>>(Wfc, Wfc_h, Wfc_l, DM*HD);

    /* 2) projections (NT, split out) */
    {
        dim3 g(HD/128, (NB*LQ)/128, 1);
        gemm_tc<true,true,true><<<g, 256>>>(qin_h,qin_l, Wq_h,Wq_l,
            nullptr, Qh_h, Qh_l, DM, DM, HD, DM, 1.f, 0,0, 0,0, 0,0);
    }
    {
        dim3 g(HD/128, (NB*LK)/128, 1);
        gemm_tc<true,true,true><<<g, 256>>>(kin_h,kin_l, Wk_h,Wk_l,
            nullptr, Kh_h, Kh_l, DM, DM, HD, DM, 1.f, 0,0, 0,0, 0,0);
        gemm_tc<true,true,true><<<g, 256>>>(vin_h,vin_l, Wv_h,Wv_l,
            nullptr, Vh_h, Vh_l, DM, DM, HD, DM, 1.f, 0,0, 0,0, 0,0);
    }

    /* 3) logits = (1/16) * Qh @ Kh^T  (fp32 out) */
    {
        dim3 g(LK/128, LQ/128, NB*NH);
        gemm_tc<true,true,false><<<g, 256>>>(Qh_h,Qh_l, Kh_h,Kh_l,
            logits, nullptr, nullptr, HD, HD, LK, DM, 0.0625f,
            (long long)LQ*HD, DM,
            (long long)LK*HD, DM,
            (long long)NH*LQ*LK, (long long)LQ*LK);
    }

    /* 4) softmax -> bf16 P + head-mean into d_out tail */
    softmax_mean_kernel<<<NB*LQ, 256>>>(out + Y_SIZE);

    /* 5) O = P @ Vh (NN, A single-plane, split out) */
    {
        dim3 g(DM/128, LQ/128, NB*NH);
        gemm_tc<false,false,true><<<g, 256>>>(P, nullptr, Vh_h,Vh_l,
            nullptr, O_h, O_l, LK, HD, HD, LK, 1.f,
            (long long)NH*LQ*LK, (long long)LQ*LK,
            (long long)LK*HD, DM,
            (long long)LQ*HD, DM);
    }

    /* 6) fc (NT, fp32 out) */
    {
        dim3 g(DM/128, (NB*LQ)/128, 1);
        gemm_tc<true,true,false><<<g, 256>>>(O_h,O_l, Wfc_h,Wfc_l,
            fc, nullptr, nullptr, HD, HD, DM, HD, 1.f, 0,0, 0,0, 0,0);
    }

    /* 7) residual + LayerNorm -> y */
    ln_kernel<<<NB*LQ, 256>>>(tgt, ln_g, ln_b, out);
}

// round 8
// speedup vs baseline: 1.8560x; 1.1068x over previous
#include <cuda_runtime.h>
#include <cuda_bf16.h>
#include <stdint.h>
#include <math.h>

#define LQ    1024
#define LK    4096
#define NB    8
#define DM    256
#define NH    4
#define HD    (NH*DM)              /* 1024 */
#define Y_SIZE (LQ*NB*DM)          /* 2097152 */

typedef __nv_bfloat16  bf16;
typedef __nv_bfloat162 bf162;

/* ---------------- scratch (device globals; no allocation allowed) -------- */
__device__ bf16  g_qin_h[NB*LQ*DM],  g_qin_l[NB*LQ*DM];
__device__ bf16  g_kin_h[NB*LK*DM],  g_kin_l[NB*LK*DM];
__device__ bf16  g_vin_h[NB*LK*DM];
__device__ bf16  g_Wq_h[HD*DM],  g_Wq_l[HD*DM];
__device__ bf16  g_Wk_h[HD*DM],  g_Wk_l[HD*DM];
__device__ bf16  g_Wv_h[HD*DM],  g_Wv_l[HD*DM];
__device__ bf16  g_Wfc_h[DM*HD], g_Wfc_l[DM*HD];
__device__ bf16  g_Qh_h[NB*LQ*HD], g_Qh_l[NB*LQ*HD];
__device__ bf16  g_Kh_h[NB*LK*HD], g_Kh_l[NB*LK*HD];
__device__ bf16  g_V  [NB*LK*HD];
__device__ float g_logits[(long long)NB*NH*LQ*LK];
__device__ bf16  g_P[(long long)NB*NH*LQ*LK];
__device__ bf16  g_O_h[NB*LQ*HD], g_O_l[NB*LQ*HD];
__device__ float g_fc[NB*LQ*DM];

/* ---------------- helpers ------------------------------------------------ */
__device__ __forceinline__ void split2(float a, float b, bf162& h, bf162& l) {
    bf16 ha = __float2bfloat16(a);
    bf16 hb = __float2bfloat16(b);
    h = __halves2bfloat162(ha, hb);
    l = __halves2bfloat162(__float2bfloat16(a - __bfloat162float(ha)),
                           __float2bfloat16(b - __bfloat162float(hb)));
}

#define LDSM4(R, addr) \
    asm volatile("ldmatrix.sync.aligned.m8n8.x4.shared.b16 {%0,%1,%2,%3}, [%4];" \
        : "=r"((R)[0]),"=r"((R)[1]),"=r"((R)[2]),"=r"((R)[3]) : "r"(addr))
#define LDSM4T(R, addr) \
    asm volatile("ldmatrix.sync.aligned.m8n8.x4.trans.shared.b16 {%0,%1,%2,%3}, [%4];" \
        : "=r"((R)[0]),"=r"((R)[1]),"=r"((R)[2]),"=r"((R)[3]) : "r"(addr))
#define MMA16816(D, A, B0, B1) \
    asm volatile("mma.sync.aligned.m16n8k16.row.col.f32.bf16.bf16.f32 " \
        "{%0,%1,%2,%3}, {%4,%5,%6,%7}, {%8,%9}, {%0,%1,%2,%3};" \
        : "+f"((D)[0]),"+f"((D)[1]),"+f"((D)[2]),"+f"((D)[3]) \
        : "r"((A)[0]),"r"((A)[1]),"r"((A)[2]),"r"((A)[3]), "r"(B0),"r"(B1))

/* ---------------- prep: seq-first -> batch-first (+pos adds), split ------ */
__global__ void prep_q_kernel(const float* __restrict__ tgt,
                              const float* __restrict__ qpos) {
    int t = (blockIdx.x * blockDim.x + threadIdx.x) * 4;
    if (t >= NB*LQ*DM) return;
    int d = t % DM;
    int r = t / DM;
    int q = r % LQ;
    int b = r / LQ;
    int src = (q*NB + b)*DM + d;
    float4 a = *(const float4*)(tgt  + src);
    float4 p = *(const float4*)(qpos + src);
    bf162 h01, l01, h23, l23;
    split2(a.x+p.x, a.y+p.y, h01, l01);
    split2(a.z+p.z, a.w+p.w, h23, l23);
    *(bf162*)(g_qin_h + t)     = h01;
    *(bf162*)(g_qin_h + t + 2) = h23;
    *(bf162*)(g_qin_l + t)     = l01;
    *(bf162*)(g_qin_l + t + 2) = l23;
}

__global__ void prep_kv_kernel(const float* __restrict__ mem,
                               const float* __restrict__ pos) {
    int t = (blockIdx.x * blockDim.x + threadIdx.x) * 4;
    if (t >= NB*LK*DM) return;
    int d = t % DM;
    int r = t / DM;
    int k = r % LK;
    int b = r / LK;
    int src = (k*NB + b)*DM + d;
    float4 m = *(const float4*)(mem + src);
    float4 p = *(const float4*)(pos + src);
    bf162 h01, l01, h23, l23;
    split2(m.x+p.x, m.y+p.y, h01, l01);
    split2(m.z+p.z, m.w+p.w, h23, l23);
    *(bf162*)(g_kin_h + t)     = h01;
    *(bf162*)(g_kin_h + t + 2) = h23;
    *(bf162*)(g_kin_l + t)     = l01;
    *(bf162*)(g_kin_l + t + 2) = l23;
    /* V input: hi plane only (consumed at bf16 precision downstream) */
    bf162 vh01 = __halves2bfloat162(__float2bfloat16(m.x), __float2bfloat16(m.y));
    bf162 vh23 = __halves2bfloat162(__float2bfloat16(m.z), __float2bfloat16(m.w));
    *(bf162*)(g_vin_h + t)     = vh01;
    *(bf162*)(g_vin_h + t + 2) = vh23;
}

__global__ void convw_kernel(const float* __restrict__ W,
                             bf16* __restrict__ Wh, bf16* __restrict__ Wl, int n) {
    int t = (blockIdx.x * blockDim.x + threadIdx.x) * 4;
    if (t >= n) return;
    float4 v = *(const float4*)(W + t);
    bf162 h01, l01, h23, l23;
    split2(v.x, v.y, h01, l01);
    split2(v.z, v.w, h23, l23);
    *(bf162*)(Wh + t)     = h01;
    *(bf162*)(Wh + t + 2) = h23;
    *(bf162*)(Wl + t)     = l01;
    *(bf162*)(Wl + t + 2) = l23;
}

/* ================== mma.sync GEMM (pre-split planes) =====================
 * C = alpha * sum_k A[m,k] * (TRANS_B ? B[n,k] : B[k,n])
 * Passes: AhBh (+AlBh if A_SPLIT) (+AhBl if B_SPLIT).
 * OUT_MODE: 0 = fp32, 1 = split bf16 hi/lo planes, 2 = single bf16 plane.
 * CTA 128x128, 8 warps (4x2), warp 32x64, k-step 16, double-buffered smem.
 * ========================================================================= */
#define APITCH 40
#define BPITCH 136

template<bool TRANS_B, bool A_SPLIT, bool B_SPLIT, int OUT_MODE>
__global__ void __launch_bounds__(256)
gemm_tc(const bf16* __restrict__ Ah, const bf16* __restrict__ Al,
        const bf16* __restrict__ Bh, const bf16* __restrict__ Bl,
        float* __restrict__ C, bf16* __restrict__ Ch, bf16* __restrict__ Cl,
        int lda, int ldb, int ldc, int K, float alpha,
        long long sA0, long long sA1,
        long long sB0, long long sB1,
        long long sC0, long long sC1) {
    int z = blockIdx.z;
    int z0 = z / NH, z1 = z % NH;
    long long ao = z0*sA0 + z1*sA1;
    long long bo = z0*sB0 + z1*sB1;
    long long co = z0*sC0 + z1*sC1;
    Ah += ao; if (A_SPLIT) Al += ao;
    Bh += bo; if (B_SPLIT) Bl += bo;
    if (OUT_MODE == 0) C += co; else { Ch += co; if (OUT_MODE == 1) Cl += co; }

    const int m0 = blockIdx.y * 128;
    const int n0 = blockIdx.x * 128;

    const int tid  = threadIdx.x;
    const int lane = tid & 31;
    const int warp = tid >> 5;
    const int wm   = warp >> 1;
    const int wn   = warp & 1;

    constexpr int BSZ = TRANS_B ? 128*APITCH : (B_SPLIT ? 32 : 16)*BPITCH;
    __shared__ __align__(16) bf16 As[2][128*APITCH];
    __shared__ __align__(16) bf16 Bs[2][BSZ];

    const int la_row = tid >> 1;
    const int la_h8  = (tid & 1) * 8;
    const int lb_kr  = tid >> 4;
    const int lb_c8  = (tid & 15) * 8;

    uint4 pa_h, pa_l, pb_h, pb_l;

    float acc[2][8][4];
    #pragma unroll
    for (int i = 0; i < 2; i++)
        #pragma unroll
        for (int j = 0; j < 8; j++)
            #pragma unroll
            for (int c = 0; c < 4; c++) acc[i][j][c] = 0.f;

    const int nk = K / 16;

    auto g_load = [&](int k0) {
        pa_h = *(const uint4*)(Ah + (long long)(m0 + la_row)*lda + k0 + la_h8);
        if (A_SPLIT)
            pa_l = *(const uint4*)(Al + (long long)(m0 + la_row)*lda + k0 + la_h8);
        if (TRANS_B) {
            pb_h = *(const uint4*)(Bh + (long long)(n0 + la_row)*ldb + k0 + la_h8);
            if (B_SPLIT)
                pb_l = *(const uint4*)(Bl + (long long)(n0 + la_row)*ldb + k0 + la_h8);
        } else {
            pb_h = *(const uint4*)(Bh + (long long)(k0 + lb_kr)*ldb + n0 + lb_c8);
            if (B_SPLIT)
                pb_l = *(const uint4*)(Bl + (long long)(k0 + lb_kr)*ldb + n0 + lb_c8);
        }
    };

    auto s_store = [&](int buf) {
        *(uint4*)&As[buf][la_row*APITCH + la_h8] = pa_h;
        if (A_SPLIT)
            *(uint4*)&As[buf][la_row*APITCH + 16 + la_h8] = pa_l;
        if (TRANS_B) {
            *(uint4*)&Bs[buf][la_row*APITCH + la_h8] = pb_h;
            if (B_SPLIT)
                *(uint4*)&Bs[buf][la_row*APITCH + 16 + la_h8] = pb_l;
        } else {
            *(uint4*)&Bs[buf][lb_kr*BPITCH + lb_c8] = pb_h;
            if (B_SPLIT)
                *(uint4*)&Bs[buf][(16 + lb_kr)*BPITCH + lb_c8] = pb_l;
        }
    };

    auto compute = [&](int buf) {
        uint32_t a_h[2][4], a_l[2][4];
        #pragma unroll
        for (int mi = 0; mi < 2; mi++) {
            int row = wm*32 + mi*16 + (lane & 7) + ((lane >> 3) & 1)*8;
            uint32_t ad = (uint32_t)__cvta_generic_to_shared(
                &As[buf][row*APITCH + ((lane >> 4) & 1)*8]);
            LDSM4(a_h[mi], ad);
            if (A_SPLIT) LDSM4(a_l[mi], ad + 32);
        }
        #pragma unroll
        for (int g = 0; g < 4; g++) {
            uint32_t bh[4], bl[4];
            if (TRANS_B) {
                int n = wn*64 + g*16 + (lane & 7) + ((lane >> 4) & 1)*8;
                uint32_t bd = (uint32_t)__cvta_generic_to_shared(
                    &Bs[buf][n*APITCH + ((lane >> 3) & 1)*8]);
                LDSM4(bh, bd);
                if (B_SPLIT) LDSM4(bl, bd + 32);
            } else {
                int kr = (lane & 7) + ((lane >> 3) & 1)*8;
                int nc = wn*64 + g*16 + ((lane >> 4) & 1)*8;
                uint32_t bd = (uint32_t)__cvta_generic_to_shared(
                    &Bs[buf][kr*BPITCH + nc]);
                LDSM4T(bh, bd);
                if (B_SPLIT) LDSM4T(bl, bd + 16*BPITCH*2);
            }
            #pragma unroll
            for (int t = 0; t < 2; t++)
                #pragma unroll
                for (int mi = 0; mi < 2; mi++)
                    MMA16816(acc[mi][g*2 + t], a_h[mi], bh[2*t], bh[2*t+1]);
            if (A_SPLIT) {
                #pragma unroll
                for (int t = 0; t < 2; t++)
                    #pragma unroll
                    for (int mi = 0; mi < 2; mi++)
                        MMA16816(acc[mi][g*2 + t], a_l[mi], bh[2*t], bh[2*t+1]);
            }
            if (B_SPLIT) {
                #pragma unroll
                for (int t = 0; t < 2; t++)
                    #pragma unroll
                    for (int mi = 0; mi < 2; mi++)
                        MMA16816(acc[mi][g*2 + t], a_h[mi], bl[2*t], bl[2*t+1]);
            }
        }
    };

    g_load(0);
    s_store(0);
    __syncthreads();

    for (int ks = 0; ks < nk; ks++) {
        int buf = ks & 1;
        bool more = (ks + 1) < nk;
        if (more) g_load((ks + 1) * 16);
        compute(buf);
        if (more) s_store(buf ^ 1);
        __syncthreads();
    }

    #pragma unroll
    for (int mi = 0; mi < 2; mi++) {
        #pragma unroll
        for (int nj = 0; nj < 8; nj++) {
            int row = m0 + wm*32 + mi*16 + (lane >> 2);
            int col = n0 + wn*64 + nj*8 + (lane & 3)*2;
            float v0 = alpha*acc[mi][nj][0], v1 = alpha*acc[mi][nj][1];
            float v2 = alpha*acc[mi][nj][2], v3 = alpha*acc[mi][nj][3];
            if (OUT_MODE == 1) {
                bf162 h, l;
                split2(v0, v1, h, l);
                *(bf162*)(Ch + (long long)row*ldc + col) = h;
                *(bf162*)(Cl + (long long)row*ldc + col) = l;
                split2(v2, v3, h, l);
                *(bf162*)(Ch + (long long)(row+8)*ldc + col) = h;
                *(bf162*)(Cl + (long long)(row+8)*ldc + col) = l;
            } else if (OUT_MODE == 2) {
                *(bf162*)(Ch + (long long)row*ldc + col) =
                    __halves2bfloat162(__float2bfloat16(v0), __float2bfloat16(v1));
                *(bf162*)(Ch + (long long)(row+8)*ldc + col) =
                    __halves2bfloat162(__float2bfloat16(v2), __float2bfloat16(v3));
            } else {
                float2 a; a.x = v0; a.y = v1;
                float2 b; b.x = v2; b.y = v3;
                *(float2*)(C + (long long)row*ldc + col)     = a;
                *(float2*)(C + (long long)(row+8)*ldc + col) = b;
            }
        }
    }
}

/* ---------------- fused softmax (P -> bf16) + head-mean ------------------ */
__device__ __forceinline__ float blk_reduce_max(float v, float* red) {
    red[threadIdx.x] = v; __syncthreads();
    for (int s = 128; s > 0; s >>= 1) {
        if (threadIdx.x < s) red[threadIdx.x] = fmaxf(red[threadIdx.x], red[threadIdx.x+s]);
        __syncthreads();
    }
    float r = red[0]; __syncthreads(); return r;
}
__device__ __forceinline__ float blk_reduce_sum(float v, float* red) {
    red[threadIdx.x] = v; __syncthreads();
    for (int s = 128; s > 0; s >>= 1) {
        if (threadIdx.x < s) red[threadIdx.x] += red[threadIdx.x+s];
        __syncthreads();
    }
    float r = red[0]; __syncthreads(); return r;
}

__global__ void __launch_bounds__(256)
softmax_mean_kernel(float* __restrict__ out_mean) {
    const int row = blockIdx.x;      /* b*LQ + q */
    const int b = row / LQ;
    const int q = row % LQ;
    const int tid = threadIdx.x;
    __shared__ float red[256];

    float mean_acc[LK/256];
    #pragma unroll
    for (int i = 0; i < LK/256; i++) mean_acc[i] = 0.f;

    for (int h = 0; h < NH; h++) {
        long long off = ((long long)((b*NH + h)*LQ + q)) * LK;
        const float* base = g_logits + off;
        float v[LK/256];
        float mx = -1e30f;
        #pragma unroll
        for (int i = 0; i < LK/256; i++) {
            v[i] = base[i*256 + tid];
            mean_acc[i] += v[i];
            mx = fmaxf(mx, v[i]);
        }
        mx = blk_reduce_max(mx, red);
        float s = 0.f;
        #pragma unroll
        for (int i = 0; i < LK/256; i++) { v[i] = __expf(v[i] - mx); s += v[i]; }
        s = blk_reduce_sum(s, red);
        float inv = 1.f / s;
        bf16* pdst = g_P + off;
        #pragma unroll
        for (int i = 0; i < LK/256; i++)
            pdst[i*256 + tid] = __float2bfloat16(v[i] * inv);
    }
    float* mdst = out_mean + (long long)row * LK;
    #pragma unroll
    for (int i = 0; i < LK/256; i++) mdst[i*256 + tid] = mean_acc[i] * 0.25f;
}

/* ---------------- residual + LayerNorm ----------------------------------- */
__global__ void __launch_bounds__(256)
ln_kernel(const float* __restrict__ tgt,
          const float* __restrict__ gamma,
          const float* __restrict__ beta,
          float* __restrict__ y) {
    const int row = blockIdx.x;
    const int b = row / LQ;
    const int q = row % LQ;
    const int d = threadIdx.x;
    __shared__ float red[256];

    float x = g_fc[row*DM + d] + tgt[(q*NB + b)*DM + d];
    float mu = blk_reduce_sum(x, red) * (1.f/DM);
    float diff = x - mu;
    float var = blk_reduce_sum(diff*diff, red) * (1.f/DM);
    y[(q*NB + b)*DM + d] = diff * rsqrtf(var + 1e-5f) * gamma[d] + beta[d];
}

/* ---------------- launch ------------------------------------------------- */
extern "C" void kernel_launch(void* const* d_in, const int* in_sizes, int n_in,
                              void* d_out, int out_size) {
    const float* tgt  = (const float*)d_in[0];
    const float* mem  = (const float*)d_in[1];
    const float* pos  = (const float*)d_in[2];
    const float* qpos = (const float*)d_in[3];
    const float* Wq   = (const float*)d_in[4];
    const float* Wk   = (const float*)d_in[5];
    const float* Wv   = (const float*)d_in[6];
    const float* Wfc  = (const float*)d_in[7];
    const float* ln_g = (const float*)d_in[8];
    const float* ln_b = (const float*)d_in[9];
    float* out = (float*)d_out;

    bf16 *qin_h,*qin_l,*kin_h,*kin_l,*vin_h;
    bf16 *Wq_h,*Wq_l,*Wk_h,*Wk_l,*Wv_h,*Wv_l,*Wfc_h,*Wfc_l;
    bf16 *Qh_h,*Qh_l,*Kh_h,*Kh_l,*V,*P,*O_h,*O_l;
    float *logits,*fc;
    cudaGetSymbolAddress((void**)&qin_h, g_qin_h); cudaGetSymbolAddress((void**)&qin_l, g_qin_l);
    cudaGetSymbolAddress((void**)&kin_h, g_kin_h); cudaGetSymbolAddress((void**)&kin_l, g_kin_l);
    cudaGetSymbolAddress((void**)&vin_h, g_vin_h);
    cudaGetSymbolAddress((void**)&Wq_h,  g_Wq_h);  cudaGetSymbolAddress((void**)&Wq_l,  g_Wq_l);
    cudaGetSymbolAddress((void**)&Wk_h,  g_Wk_h);  cudaGetSymbolAddress((void**)&Wk_l,  g_Wk_l);
    cudaGetSymbolAddress((void**)&Wv_h,  g_Wv_h);  cudaGetSymbolAddress((void**)&Wv_l,  g_Wv_l);
    cudaGetSymbolAddress((void**)&Wfc_h, g_Wfc_h); cudaGetSymbolAddress((void**)&Wfc_l, g_Wfc_l);
    cudaGetSymbolAddress((void**)&Qh_h,  g_Qh_h);  cudaGetSymbolAddress((void**)&Qh_l,  g_Qh_l);
    cudaGetSymbolAddress((void**)&Kh_h,  g_Kh_h);  cudaGetSymbolAddress((void**)&Kh_l,  g_Kh_l);
    cudaGetSymbolAddress((void**)&V,     g_V);
    cudaGetSymbolAddress((void**)&P,     g_P);
    cudaGetSymbolAddress((void**)&O_h,   g_O_h);   cudaGetSymbolAddress((void**)&O_l,   g_O_l);
    cudaGetSymbolAddress((void**)&logits, g_logits);
    cudaGetSymbolAddress((void**)&fc,     g_fc);

    /* 1) transpose + pos adds + split; weight split */
    prep_q_kernel <<<(NB*LQ*DM/4 + 255)/256, 256>>>(tgt, qpos);
    prep_kv_kernel<<<(NB*LK*DM/4 + 255)/256, 256>>>(mem, pos);
    convw_kernel<<<(HD*DM/4 + 255)/256, 256>>>(Wq,  Wq_h,  Wq_l,  HD*DM);
    convw_kernel<<<(HD*DM/4 + 255)/256, 256>>>(Wk,  Wk_h,  Wk_l,  HD*DM);
    convw_kernel<<<(HD*DM/4 + 255)/256, 256>>>(Wv,  Wv_h,  Wv_l,  HD*DM);
    convw_kernel<<<(DM*HD/4 + 255)/256, 256>>>(Wfc, Wfc_h, Wfc_l, DM*HD);

    /* 2) projections (NT) */
    {
        dim3 g(HD/128, (NB*LQ)/128, 1);
        gemm_tc<true,true,true,1><<<g, 256>>>(qin_h,qin_l, Wq_h,Wq_l,
            nullptr, Qh_h, Qh_l, DM, DM, HD, DM, 1.f, 0,0, 0,0, 0,0);
    }
    {
        dim3 g(HD/128, (NB*LK)/128, 1);
        gemm_tc<true,true,true,1><<<g, 256>>>(kin_h,kin_l, Wk_h,Wk_l,
            nullptr, Kh_h, Kh_l, DM, DM, HD, DM, 1.f, 0,0, 0,0, 0,0);
        /* V-proj: 2-pass (vin hi only), single bf16 output plane */
        gemm_tc<true,false,true,2><<<g, 256>>>(vin_h,nullptr, Wv_h,Wv_l,
            nullptr, V, nullptr, DM, DM, HD, DM, 1.f, 0,0, 0,0, 0,0);
    }

    /* 3) logits = (1/16) * Qh @ Kh^T  (full 3-pass, fp32 out) */
    {
        dim3 g(LK/128, LQ/128, NB*NH);
        gemm_tc<true,true,true,0><<<g, 256>>>(Qh_h,Qh_l, Kh_h,Kh_l,
            logits, nullptr, nullptr, HD, HD, LK, DM, 0.0625f,
            (long long)LQ*HD, DM,
            (long long)LK*HD, DM,
            (long long)NH*LQ*LK, (long long)LQ*LK);
    }

    /* 4) softmax -> bf16 P + head-mean into d_out tail */
    softmax_mean_kernel<<<NB*LQ, 256>>>(out + Y_SIZE);

    /* 5) O = P @ V (NN, 1-pass bf16 x bf16, split out) */
    {
        dim3 g(DM/128, LQ/128, NB*NH);
        gemm_tc<false,false,false,1><<<g, 256>>>(P, nullptr, V, nullptr,
            nullptr, O_h, O_l, LK, HD, HD, LK, 1.f,
            (long long)NH*LQ*LK, (long long)LQ*LK,
            (long long)LK*HD, DM,
            (long long)LQ*HD, DM);
    }

    /* 6) fc (NT, 3-pass, fp32 out) */
    {
        dim3 g(DM/128, (NB*LQ)/128, 1);
        gemm_tc<true,true,true,0><<<g, 256>>>(O_h,O_l, Wfc_h,Wfc_l,
            fc, nullptr, nullptr, HD, HD, DM, HD, 1.f, 0,0, 0,0, 0,0);
    }

    /* 7) residual + LayerNorm -> y */
    ln_kernel<<<NB*LQ, 256>>>(tgt, ln_g, ln_b, out);
}